// round 10
// baseline (speedup 1.0000x reference)
#include <cuda_runtime.h>
#include <cstdint>

// ============================================================================
// AmbientSphericalBrownianMotion — Stratonovich-Heun BM on S^2, N=4.2M pts,
// 100 steps. Bit-exact JAX threefry2x32 random bits (partitionable:
// bits0 ^ bits1). Issue-bound: threefry adds split IMAD(fma pipe)/IADD3(alu),
// key injections fused into next round's add via IADD3, warp-uniform
// erfinv tail (no divergent sync).
// ============================================================================

#define MAX_STEPS 4096
struct __align__(16) StepKey {
    uint4 a;   // k0, k1, k2, k2+1
    uint4 b;   // k0+2, k1+3, k2+4, k0+5
};
__device__ StepKey g_step_keys[MAX_STEPS];

__device__ __forceinline__ uint32_t rotl32(uint32_t v, int r) {
    return __funnelshift_l(v, v, r);
}

// add via IMAD (fma pipe): d = a*one + c, with `one` runtime-opaque == 1
__device__ __forceinline__ uint32_t imad1(uint32_t a, uint32_t one, uint32_t c) {
    uint32_t d;
    asm("mad.lo.u32 %0, %1, %2, %3;" : "=r"(d) : "r"(a), "r"(one), "r"(c));
    return d;
}

// threefry round, add on fma pipe; rot+xor on alu pipe
__device__ __forceinline__ void tfr(uint32_t& x0, uint32_t& x1, int r, uint32_t one) {
    x0 = imad1(x0, one, x1);
    x1 = rotl32(x1, r) ^ x0;
}

// first round of a group with the x0 key-injection fused: x0 = x0 + kx + x1
// (single IADD3 on the alu pipe)
__device__ __forceinline__ void tfr_fused(uint32_t& x0, uint32_t& x1, int r,
                                          uint32_t kx) {
    x0 = x0 + kx + x1;
    x1 = rotl32(x1, r) ^ x0;
}

// JAX partitionable random_bits(32): bits0 ^ bits1, sign-flip folded into the
// final 3-input LOP3 (for the I2F uniform path).
__device__ __forceinline__ int32_t tf_sbits(const StepKey& k, uint32_t x1init,
                                            uint32_t one) {
    uint32_t x0 = k.a.x;   // c0 = 0, so x0 = k0
    uint32_t x1 = x1init;  // c1 + k1, pre-added by caller
    tfr(x0, x1, 13, one); tfr(x0, x1, 15, one);
    tfr(x0, x1, 26, one); tfr(x0, x1, 6,  one);
    x1 += k.a.w;                       // +(k2+1)
    tfr_fused(x0, x1, 17, k.a.y);      // x0 += k1, fused
    tfr(x0, x1, 29, one); tfr(x0, x1, 16, one); tfr(x0, x1, 24, one);
    x1 += k.b.x;                       // +(k0+2)
    tfr_fused(x0, x1, 13, k.a.z);      // x0 += k2, fused
    tfr(x0, x1, 15, one); tfr(x0, x1, 26, one); tfr(x0, x1, 6, one);
    x1 += k.b.y;                       // +(k1+3)
    tfr_fused(x0, x1, 17, k.a.x);      // x0 += k0, fused
    tfr(x0, x1, 29, one); tfr(x0, x1, 16, one); tfr(x0, x1, 24, one);
    x1 += k.b.z;                       // +(k2+4)
    tfr_fused(x0, x1, 13, k.a.y);      // x0 += k1, fused
    tfr(x0, x1, 15, one); tfr(x0, x1, 26, one); tfr(x0, x1, 6, one);
    return (int32_t)((x0 + k.a.z) ^ (x1 + k.b.w) ^ 0x80000000u);
}

// ---- fast-math primitives ----
__device__ __forceinline__ float lg2_fast(float x) {
    float r; asm("lg2.approx.f32 %0, %1;" : "=f"(r) : "f"(x)); return r;
}
__device__ __forceinline__ float rcp_fast(float x) {
    float r; asm("rcp.approx.f32 %0, %1;" : "=f"(r) : "f"(x)); return r;
}
__device__ __forceinline__ float rsqrt_fast(float x) {
    float r; asm("rsqrt.approx.f32 %0, %1;" : "=f"(r) : "f"(x)); return r;
}
__device__ __forceinline__ float sqrt_fast(float x) {
    float r; asm("sqrt.approx.f32 %0, %1;" : "=f"(r) : "f"(x)); return r;
}

// signed bits -> uniform(-1,1) -> sqrt2*erfinv(u)*sqrt_dt  (scale = sqrt2*sqrt_dt)
// Central branch always evaluated; rare tail handled warp-uniformly (no
// divergent BSSY/BSYNC). Per-lane results identical to the branchy version.
__device__ __forceinline__ float normal_from_sbits(int32_t sb, float scale) {
    float u  = __int2float_rn(sb) * 4.6566128730773926e-10f;   // 2^-31
    float us = u * scale;
    float L  = fmaxf(lg2_fast(fmaf(-u, u, 1.0f)), -23.0058f);  // log2(1-u^2)
    float m  = L * -0.69314718f;                               // w = -ln(1-u^2)
    float w  = m - 2.5f;
    float p;
    p =            2.81022636e-08f;
    p = fmaf(p, w, 3.43273939e-07f);
    p = fmaf(p, w, -3.5233877e-06f);
    p = fmaf(p, w, -4.39150654e-06f);
    p = fmaf(p, w, 0.00021858087f);
    p = fmaf(p, w, -0.00125372503f);
    p = fmaf(p, w, -0.00417768164f);
    p = fmaf(p, w, 0.246640727f);
    p = fmaf(p, w, 1.50140941f);
    bool tail = (m >= 5.0f);
    if (__any_sync(0xffffffffu, tail)) {
        float wt = sqrt_fast(m) - 3.0f;
        float pt;
        pt =             -0.000200214257f;
        pt = fmaf(pt, wt, 0.000100950558f);
        pt = fmaf(pt, wt, 0.00134934322f);
        pt = fmaf(pt, wt, -0.00367342844f);
        pt = fmaf(pt, wt, 0.00573950773f);
        pt = fmaf(pt, wt, -0.0076224613f);
        pt = fmaf(pt, wt, 0.00943887047f);
        pt = fmaf(pt, wt, 1.00167406f);
        pt = fmaf(pt, wt, 2.83297682f);
        p = tail ? pt : p;
    }
    return p * us;
}

__device__ __forceinline__ float dot3(float a0, float a1, float a2,
                                      float b0, float b1, float b2) {
    return fmaf(a2, b2, fmaf(a1, b1, a0 * b0));
}

// ---------------------------------------------------------------------------
// Pre-kernel: per-step folded keys + precomputed injection constants.
//   fold_in(key(1), s) = threefry((0,1),(0,s))
// ---------------------------------------------------------------------------
__device__ __forceinline__ void tfr_p(uint32_t& x0, uint32_t& x1, int r) {
    x0 += x1; x1 = rotl32(x1, r) ^ x0;
}
__global__ void keys_kernel(const int* __restrict__ steps_ptr) {
    int steps = *steps_ptr;
    if (steps > MAX_STEPS) steps = MAX_STEPS;
    for (int s = threadIdx.x; s < steps; s += blockDim.x) {
        const uint32_t k0 = 0u, k1 = 1u;
        const uint32_t k2 = k0 ^ k1 ^ 0x1BD11BDAu;
        uint32_t x0 = k0, x1 = (uint32_t)s + k1;
        tfr_p(x0,x1,13); tfr_p(x0,x1,15); tfr_p(x0,x1,26); tfr_p(x0,x1,6);
        x0 += k1; x1 += k2 + 1u;
        tfr_p(x0,x1,17); tfr_p(x0,x1,29); tfr_p(x0,x1,16); tfr_p(x0,x1,24);
        x0 += k2; x1 += k0 + 2u;
        tfr_p(x0,x1,13); tfr_p(x0,x1,15); tfr_p(x0,x1,26); tfr_p(x0,x1,6);
        x0 += k0; x1 += k1 + 3u;
        tfr_p(x0,x1,17); tfr_p(x0,x1,29); tfr_p(x0,x1,16); tfr_p(x0,x1,24);
        x0 += k1; x1 += k2 + 4u;
        tfr_p(x0,x1,13); tfr_p(x0,x1,15); tfr_p(x0,x1,26); tfr_p(x0,x1,6);
        uint32_t fk0 = x0 + k2;
        uint32_t fk1 = x1 + k0 + 5u;
        uint32_t fk2 = fk0 ^ fk1 ^ 0x1BD11BDAu;
        StepKey sk;
        sk.a = make_uint4(fk0, fk1, fk2, fk2 + 1u);
        sk.b = make_uint4(fk0 + 2u, fk1 + 3u, fk2 + 4u, fk0 + 5u);
        g_step_keys[s] = sk;
    }
}

// ---------------------------------------------------------------------------
// Main kernel: one thread per point, full trajectory in registers.
// ---------------------------------------------------------------------------
__global__ void __launch_bounds__(256)
sbm_kernel(const float* __restrict__ xin,
           const int* __restrict__ t_ptr,
           const int* __restrict__ steps_ptr,
           float* __restrict__ out, int n) {
    int i = blockIdx.x * blockDim.x + threadIdx.x;
    if (i >= n) return;

    const int steps = *steps_ptr;
    const float dt = (float)(*t_ptr) / (float)steps;
    const float scale = 1.4142135381698608f * sqrtf(dt);   // sqrt2 * sqrt_dt
    const uint32_t one = umin((uint32_t)steps, 1u);        // opaque 1 for IMAD

    float x0 = xin[3 * i + 0];
    float x1 = xin[3 * i + 1];
    float x2 = xin[3 * i + 2];

    const uint32_t base = 3u * (uint32_t)i;

    for (int s = 0; s < steps; ++s) {
        const StepKey k = g_step_keys[s];

        // three fresh signed random words for this (point, step)
        const uint32_t c1k = base + k.a.y;   // counter + k1, shared init
        int32_t b0 = tf_sbits(k, c1k,      one);
        int32_t b1 = tf_sbits(k, c1k + 1u, one);
        int32_t b2 = tf_sbits(k, c1k + 2u, one);

        float v0 = normal_from_sbits(b0, scale);
        float v1 = normal_from_sbits(b1, scale);
        float v2 = normal_from_sbits(b2, scale);

        // Closed-form Heun step on the sphere (||x|| == 1):
        //   a = x.v, q' = v.v - a^2
        //   r1 = (a + q') / (1 + q')
        //   z  = alpha*x + beta*v,  beta = 1 - r1/2,
        //   alpha = beta - 0.5*a*(1 - r1)
        float a  = dot3(x0, x1, x2, v0, v1, v2);
        float q  = dot3(v0, v1, v2, v0, v1, v2);
        float qp = fmaf(-a, a, q);
        float r1 = (a + qp) * rcp_fast(1.0f + qp);
        float beta  = fmaf(-0.5f, r1, 1.0f);
        float t     = 1.0f - r1;
        float alpha = fmaf(-0.5f, a * t, beta);

        float z0 = fmaf(beta, v0, alpha * x0);
        float z1 = fmaf(beta, v1, alpha * x1);
        float z2 = fmaf(beta, v2, alpha * x2);

        float inv = rsqrt_fast(dot3(z0, z1, z2, z0, z1, z2));
        x0 = z0 * inv;
        x1 = z1 * inv;
        x2 = z2 * inv;
    }

    out[3 * i + 0] = x0;
    out[3 * i + 1] = x1;
    out[3 * i + 2] = x2;
}

// ---------------------------------------------------------------------------
extern "C" void kernel_launch(void* const* d_in, const int* in_sizes, int n_in,
                              void* d_out, int out_size) {
    const float* x     = (const float*)d_in[0];
    const int*   t     = (const int*)d_in[1];
    const int*   steps = (const int*)d_in[2];
    const int n = in_sizes[0] / 3;

    keys_kernel<<<1, 256>>>(steps);

    const int threads = 256;
    const int blocks = (n + threads - 1) / threads;
    sbm_kernel<<<blocks, threads>>>(x, t, steps, (float*)d_out, n);
}

// round 11
// speedup vs baseline: 1.2551x; 1.2551x over previous
#include <cuda_runtime.h>
#include <cstdint>

// ============================================================================
// AmbientSphericalBrownianMotion — Stratonovich-Heun BM on S^2, N=4.2M pts,
// 100 steps. Bit-exact JAX threefry2x32 random bits (partitionable:
// bits0 ^ bits1). Issue-bound: threefry adds split IMAD(fma pipe)/IADD3(alu),
// key injections fused via IADD3, warp-uniform erfinv tail, software-
// pipelined key prefetch + unroll-2 to hide LDG latency in the step loop.
// ============================================================================

#define MAX_STEPS 4096
struct __align__(16) StepKey {
    uint4 a;   // k0, k1, k2, k2+1
    uint4 b;   // k0+2, k1+3, k2+4, k0+5
};
__device__ StepKey g_step_keys[MAX_STEPS + 1];   // +1: unguarded s+1 prefetch

__device__ __forceinline__ uint32_t rotl32(uint32_t v, int r) {
    return __funnelshift_l(v, v, r);
}

// add via IMAD (fma pipe): d = a*one + c, with `one` runtime-opaque == 1
__device__ __forceinline__ uint32_t imad1(uint32_t a, uint32_t one, uint32_t c) {
    uint32_t d;
    asm("mad.lo.u32 %0, %1, %2, %3;" : "=r"(d) : "r"(a), "r"(one), "r"(c));
    return d;
}

// threefry round, add on fma pipe; rot+xor on alu pipe
__device__ __forceinline__ void tfr(uint32_t& x0, uint32_t& x1, int r, uint32_t one) {
    x0 = imad1(x0, one, x1);
    x1 = rotl32(x1, r) ^ x0;
}

// first round of a group with the x0 key-injection fused: x0 = x0 + kx + x1
// (single IADD3 on the alu pipe)
__device__ __forceinline__ void tfr_fused(uint32_t& x0, uint32_t& x1, int r,
                                          uint32_t kx) {
    x0 = x0 + kx + x1;
    x1 = rotl32(x1, r) ^ x0;
}

// JAX partitionable random_bits(32): bits0 ^ bits1, sign-flip folded into the
// final 3-input LOP3 (for the I2F uniform path).
__device__ __forceinline__ int32_t tf_sbits(const StepKey& k, uint32_t x1init,
                                            uint32_t one) {
    uint32_t x0 = k.a.x;   // c0 = 0, so x0 = k0
    uint32_t x1 = x1init;  // c1 + k1, pre-added by caller
    tfr(x0, x1, 13, one); tfr(x0, x1, 15, one);
    tfr(x0, x1, 26, one); tfr(x0, x1, 6,  one);
    x1 += k.a.w;                       // +(k2+1)
    tfr_fused(x0, x1, 17, k.a.y);      // x0 += k1, fused
    tfr(x0, x1, 29, one); tfr(x0, x1, 16, one); tfr(x0, x1, 24, one);
    x1 += k.b.x;                       // +(k0+2)
    tfr_fused(x0, x1, 13, k.a.z);      // x0 += k2, fused
    tfr(x0, x1, 15, one); tfr(x0, x1, 26, one); tfr(x0, x1, 6, one);
    x1 += k.b.y;                       // +(k1+3)
    tfr_fused(x0, x1, 17, k.a.x);      // x0 += k0, fused
    tfr(x0, x1, 29, one); tfr(x0, x1, 16, one); tfr(x0, x1, 24, one);
    x1 += k.b.z;                       // +(k2+4)
    tfr_fused(x0, x1, 13, k.a.y);      // x0 += k1, fused
    tfr(x0, x1, 15, one); tfr(x0, x1, 26, one); tfr(x0, x1, 6, one);
    return (int32_t)((x0 + k.a.z) ^ (x1 + k.b.w) ^ 0x80000000u);
}

// ---- fast-math primitives ----
__device__ __forceinline__ float lg2_fast(float x) {
    float r; asm("lg2.approx.f32 %0, %1;" : "=f"(r) : "f"(x)); return r;
}
__device__ __forceinline__ float rcp_fast(float x) {
    float r; asm("rcp.approx.f32 %0, %1;" : "=f"(r) : "f"(x)); return r;
}
__device__ __forceinline__ float rsqrt_fast(float x) {
    float r; asm("rsqrt.approx.f32 %0, %1;" : "=f"(r) : "f"(x)); return r;
}
__device__ __forceinline__ float sqrt_fast(float x) {
    float r; asm("sqrt.approx.f32 %0, %1;" : "=f"(r) : "f"(x)); return r;
}

// signed bits -> uniform(-1,1) -> sqrt2*erfinv(u)*sqrt_dt  (scale = sqrt2*sqrt_dt)
// Central branch always evaluated; rare tail handled warp-uniformly (no
// divergent BSSY/BSYNC). Per-lane results identical to the branchy version.
__device__ __forceinline__ float normal_from_sbits(int32_t sb, float scale) {
    float u  = __int2float_rn(sb) * 4.6566128730773926e-10f;   // 2^-31
    float us = u * scale;
    float L  = fmaxf(lg2_fast(fmaf(-u, u, 1.0f)), -23.0058f);  // log2(1-u^2)
    float m  = L * -0.69314718f;                               // w = -ln(1-u^2)
    float w  = m - 2.5f;
    float p;
    p =            2.81022636e-08f;
    p = fmaf(p, w, 3.43273939e-07f);
    p = fmaf(p, w, -3.5233877e-06f);
    p = fmaf(p, w, -4.39150654e-06f);
    p = fmaf(p, w, 0.00021858087f);
    p = fmaf(p, w, -0.00125372503f);
    p = fmaf(p, w, -0.00417768164f);
    p = fmaf(p, w, 0.246640727f);
    p = fmaf(p, w, 1.50140941f);
    bool tail = (m >= 5.0f);
    if (__any_sync(0xffffffffu, tail)) {
        float wt = sqrt_fast(m) - 3.0f;
        float pt;
        pt =             -0.000200214257f;
        pt = fmaf(pt, wt, 0.000100950558f);
        pt = fmaf(pt, wt, 0.00134934322f);
        pt = fmaf(pt, wt, -0.00367342844f);
        pt = fmaf(pt, wt, 0.00573950773f);
        pt = fmaf(pt, wt, -0.0076224613f);
        pt = fmaf(pt, wt, 0.00943887047f);
        pt = fmaf(pt, wt, 1.00167406f);
        pt = fmaf(pt, wt, 2.83297682f);
        p = tail ? pt : p;
    }
    return p * us;
}

__device__ __forceinline__ float dot3(float a0, float a1, float a2,
                                      float b0, float b1, float b2) {
    return fmaf(a2, b2, fmaf(a1, b1, a0 * b0));
}

// ---------------------------------------------------------------------------
// Pre-kernel: per-step folded keys + precomputed injection constants.
//   fold_in(key(1), s) = threefry((0,1),(0,s))
// ---------------------------------------------------------------------------
__device__ __forceinline__ void tfr_p(uint32_t& x0, uint32_t& x1, int r) {
    x0 += x1; x1 = rotl32(x1, r) ^ x0;
}
__global__ void keys_kernel(const int* __restrict__ steps_ptr) {
    int steps = *steps_ptr;
    if (steps > MAX_STEPS) steps = MAX_STEPS;
    // fill [0, steps] inclusive: entry [steps] is a valid dummy so the main
    // loop's s+1 prefetch never reads uninitialized/out-of-bounds memory
    for (int s = threadIdx.x; s <= steps; s += blockDim.x) {
        const uint32_t k0 = 0u, k1 = 1u;
        const uint32_t k2 = k0 ^ k1 ^ 0x1BD11BDAu;
        uint32_t x0 = k0, x1 = (uint32_t)s + k1;
        tfr_p(x0,x1,13); tfr_p(x0,x1,15); tfr_p(x0,x1,26); tfr_p(x0,x1,6);
        x0 += k1; x1 += k2 + 1u;
        tfr_p(x0,x1,17); tfr_p(x0,x1,29); tfr_p(x0,x1,16); tfr_p(x0,x1,24);
        x0 += k2; x1 += k0 + 2u;
        tfr_p(x0,x1,13); tfr_p(x0,x1,15); tfr_p(x0,x1,26); tfr_p(x0,x1,6);
        x0 += k0; x1 += k1 + 3u;
        tfr_p(x0,x1,17); tfr_p(x0,x1,29); tfr_p(x0,x1,16); tfr_p(x0,x1,24);
        x0 += k1; x1 += k2 + 4u;
        tfr_p(x0,x1,13); tfr_p(x0,x1,15); tfr_p(x0,x1,26); tfr_p(x0,x1,6);
        uint32_t fk0 = x0 + k2;
        uint32_t fk1 = x1 + k0 + 5u;
        uint32_t fk2 = fk0 ^ fk1 ^ 0x1BD11BDAu;
        StepKey sk;
        sk.a = make_uint4(fk0, fk1, fk2, fk2 + 1u);
        sk.b = make_uint4(fk0 + 2u, fk1 + 3u, fk2 + 4u, fk0 + 5u);
        g_step_keys[s] = sk;
    }
}

// ---------------------------------------------------------------------------
// Main kernel: one thread per point, full trajectory in registers.
// Key for step s+1 is prefetched while step s computes (the RNG stream is
// independent of the state x, so the load retires behind ~290 instructions
// of independent work instead of stalling at the loop head).
// ---------------------------------------------------------------------------
__global__ void __launch_bounds__(256)
sbm_kernel(const float* __restrict__ xin,
           const int* __restrict__ t_ptr,
           const int* __restrict__ steps_ptr,
           float* __restrict__ out, int n) {
    int i = blockIdx.x * blockDim.x + threadIdx.x;
    if (i >= n) return;

    const int steps = *steps_ptr;
    const float dt = (float)(*t_ptr) / (float)steps;
    const float scale = 1.4142135381698608f * sqrtf(dt);   // sqrt2 * sqrt_dt
    const uint32_t one = umin((uint32_t)steps, 1u);        // opaque 1 for IMAD

    float x0 = xin[3 * i + 0];
    float x1 = xin[3 * i + 1];
    float x2 = xin[3 * i + 2];

    const uint32_t base = 3u * (uint32_t)i;

    StepKey k = g_step_keys[0];

    #pragma unroll 2
    for (int s = 0; s < steps; ++s) {
        const StepKey kn = g_step_keys[s + 1];   // prefetch next step's key

        // three fresh signed random words for this (point, step)
        const uint32_t c1k = base + k.a.y;   // counter + k1, shared init
        int32_t b0 = tf_sbits(k, c1k,      one);
        int32_t b1 = tf_sbits(k, c1k + 1u, one);
        int32_t b2 = tf_sbits(k, c1k + 2u, one);

        float v0 = normal_from_sbits(b0, scale);
        float v1 = normal_from_sbits(b1, scale);
        float v2 = normal_from_sbits(b2, scale);

        // Closed-form Heun step on the sphere (||x|| == 1):
        //   a = x.v, q' = v.v - a^2
        //   r1 = (a + q') / (1 + q')
        //   z  = alpha*x + beta*v,  beta = 1 - r1/2,
        //   alpha = beta - 0.5*a*(1 - r1)
        float a  = dot3(x0, x1, x2, v0, v1, v2);
        float q  = dot3(v0, v1, v2, v0, v1, v2);
        float qp = fmaf(-a, a, q);
        float r1 = (a + qp) * rcp_fast(1.0f + qp);
        float beta  = fmaf(-0.5f, r1, 1.0f);
        float t     = 1.0f - r1;
        float alpha = fmaf(-0.5f, a * t, beta);

        float z0 = fmaf(beta, v0, alpha * x0);
        float z1 = fmaf(beta, v1, alpha * x1);
        float z2 = fmaf(beta, v2, alpha * x2);

        float inv = rsqrt_fast(dot3(z0, z1, z2, z0, z1, z2));
        x0 = z0 * inv;
        x1 = z1 * inv;
        x2 = z2 * inv;

        k = kn;
    }

    out[3 * i + 0] = x0;
    out[3 * i + 1] = x1;
    out[3 * i + 2] = x2;
}

// ---------------------------------------------------------------------------
extern "C" void kernel_launch(void* const* d_in, const int* in_sizes, int n_in,
                              void* d_out, int out_size) {
    const float* x     = (const float*)d_in[0];
    const int*   t     = (const int*)d_in[1];
    const int*   steps = (const int*)d_in[2];
    const int n = in_sizes[0] / 3;

    keys_kernel<<<1, 256>>>(steps);

    const int threads = 256;
    const int blocks = (n + threads - 1) / threads;
    sbm_kernel<<<blocks, threads>>>(x, t, steps, (float*)d_out, n);
}

// round 13
// speedup vs baseline: 2.1771x; 1.7346x over previous
#include <cuda_runtime.h>
#include <cstdint>

// ============================================================================
// AmbientSphericalBrownianMotion — Stratovich-Heun BM on S^2, N=4.2M pts,
// 100 steps. Bit-exact JAX threefry2x32 random bits (partitionable:
// bits0 ^ bits1). alu-pipe-rt bound: ALL integer adds (round adds + every
// key injection + output adds) forced onto IMAD (fma pipe) via opaque
// multiplier; alu pipe carries only the irreducible SHF+LOP stream.
// Key prefetch + unroll-2 retained from R11.
// ============================================================================

#define MAX_STEPS 4096
struct __align__(16) StepKey {
    uint4 a;   // k0, k1, k2, k2+1
    uint4 b;   // k0+2, k1+3, k2+4, k0+5
};
__device__ StepKey g_step_keys[MAX_STEPS + 1];   // +1: unguarded s+1 prefetch

__device__ __forceinline__ uint32_t rotl32(uint32_t v, int r) {
    return __funnelshift_l(v, v, r);
}

// add via IMAD (fma pipe): d = a*one + c, with `one` runtime-opaque == 1.
// Inline asm mad.lo.u32 compiles to IMAD; ptxas cannot strength-reduce it
// back onto the alu pipe.
__device__ __forceinline__ uint32_t imad1(uint32_t a, uint32_t one, uint32_t c) {
    uint32_t d;
    asm("mad.lo.u32 %0, %1, %2, %3;" : "=r"(d) : "r"(a), "r"(one), "r"(c));
    return d;
}

// threefry round: add on fma pipe (IMAD); rot+xor on alu pipe (SHF+LOP)
__device__ __forceinline__ void tfr(uint32_t& x0, uint32_t& x1, int r, uint32_t one) {
    x0 = imad1(x0, one, x1);
    x1 = rotl32(x1, r) ^ x0;
}

// JAX partitionable random_bits(32): bits0 ^ bits1, sign-flip folded into the
// final 3-input LOP3 (for the I2F uniform path). Every key injection and the
// two output adds run as IMAD on the fma pipe: the alu pipe sees exactly
// 2 ops/round (SHF+LOP) + 1 final LOP3.
__device__ __forceinline__ int32_t tf_sbits(const StepKey& k, uint32_t x1init,
                                            uint32_t one) {
    uint32_t x0 = k.a.x;   // c0 = 0, so x0 = k0
    uint32_t x1 = x1init;  // c1 + k1, pre-added by caller
    tfr(x0, x1, 13, one); tfr(x0, x1, 15, one);
    tfr(x0, x1, 26, one); tfr(x0, x1, 6,  one);
    x0 = imad1(x0, one, k.a.y);  x1 = imad1(x1, one, k.a.w);  // +k1, +(k2+1)
    tfr(x0, x1, 17, one); tfr(x0, x1, 29, one);
    tfr(x0, x1, 16, one); tfr(x0, x1, 24, one);
    x0 = imad1(x0, one, k.a.z);  x1 = imad1(x1, one, k.b.x);  // +k2, +(k0+2)
    tfr(x0, x1, 13, one); tfr(x0, x1, 15, one);
    tfr(x0, x1, 26, one); tfr(x0, x1, 6,  one);
    x0 = imad1(x0, one, k.a.x);  x1 = imad1(x1, one, k.b.y);  // +k0, +(k1+3)
    tfr(x0, x1, 17, one); tfr(x0, x1, 29, one);
    tfr(x0, x1, 16, one); tfr(x0, x1, 24, one);
    x0 = imad1(x0, one, k.a.y);  x1 = imad1(x1, one, k.b.z);  // +k1, +(k2+4)
    tfr(x0, x1, 13, one); tfr(x0, x1, 15, one);
    tfr(x0, x1, 26, one); tfr(x0, x1, 6,  one);
    uint32_t o0 = imad1(x0, one, k.a.z);   // +k2
    uint32_t o1 = imad1(x1, one, k.b.w);   // +(k0+5)
    return (int32_t)(o0 ^ o1 ^ 0x80000000u);
}

// ---- fast-math primitives ----
__device__ __forceinline__ float lg2_fast(float x) {
    float r; asm("lg2.approx.f32 %0, %1;" : "=f"(r) : "f"(x)); return r;
}
__device__ __forceinline__ float rcp_fast(float x) {
    float r; asm("rcp.approx.f32 %0, %1;" : "=f"(r) : "f"(x)); return r;
}
__device__ __forceinline__ float rsqrt_fast(float x) {
    float r; asm("rsqrt.approx.f32 %0, %1;" : "=f"(r) : "f"(x)); return r;
}
__device__ __forceinline__ float sqrt_fast(float x) {
    float r; asm("sqrt.approx.f32 %0, %1;" : "=f"(r) : "f"(x)); return r;
}

// signed bits -> uniform(-1,1) -> sqrt2*erfinv(u)*sqrt_dt  (scale = sqrt2*sqrt_dt)
// Central branch always evaluated; rare tail handled warp-uniformly (no
// divergent BSSY/BSYNC). Per-lane results identical to the branchy version.
__device__ __forceinline__ float normal_from_sbits(int32_t sb, float scale) {
    float u  = __int2float_rn(sb) * 4.6566128730773926e-10f;   // 2^-31
    float us = u * scale;
    float L  = fmaxf(lg2_fast(fmaf(-u, u, 1.0f)), -23.0058f);  // log2(1-u^2)
    float m  = L * -0.69314718f;                               // w = -ln(1-u^2)
    float w  = m - 2.5f;
    float p;
    p =            2.81022636e-08f;
    p = fmaf(p, w, 3.43273939e-07f);
    p = fmaf(p, w, -3.5233877e-06f);
    p = fmaf(p, w, -4.39150654e-06f);
    p = fmaf(p, w, 0.00021858087f);
    p = fmaf(p, w, -0.00125372503f);
    p = fmaf(p, w, -0.00417768164f);
    p = fmaf(p, w, 0.246640727f);
    p = fmaf(p, w, 1.50140941f);
    bool tail = (m >= 5.0f);
    if (__any_sync(0xffffffffu, tail)) {
        float wt = sqrt_fast(m) - 3.0f;
        float pt;
        pt =             -0.000200214257f;
        pt = fmaf(pt, wt, 0.000100950558f);
        pt = fmaf(pt, wt, 0.00134934322f);
        pt = fmaf(pt, wt, -0.00367342844f);
        pt = fmaf(pt, wt, 0.00573950773f);
        pt = fmaf(pt, wt, -0.0076224613f);
        pt = fmaf(pt, wt, 0.00943887047f);
        pt = fmaf(pt, wt, 1.00167406f);
        pt = fmaf(pt, wt, 2.83297682f);
        p = tail ? pt : p;
    }
    return p * us;
}

__device__ __forceinline__ float dot3(float a0, float a1, float a2,
                                      float b0, float b1, float b2) {
    return fmaf(a2, b2, fmaf(a1, b1, a0 * b0));
}

// ---------------------------------------------------------------------------
// Pre-kernel: per-step folded keys + precomputed injection constants.
//   fold_in(key(1), s) = threefry((0,1),(0,s))
// ---------------------------------------------------------------------------
__device__ __forceinline__ void tfr_p(uint32_t& x0, uint32_t& x1, int r) {
    x0 += x1; x1 = rotl32(x1, r) ^ x0;
}
__global__ void keys_kernel(const int* __restrict__ steps_ptr) {
    int steps = *steps_ptr;
    if (steps > MAX_STEPS) steps = MAX_STEPS;
    // fill [0, steps] inclusive: entry [steps] is a valid dummy so the main
    // loop's s+1 prefetch never reads uninitialized/out-of-bounds memory
    for (int s = threadIdx.x; s <= steps; s += blockDim.x) {
        const uint32_t k0 = 0u, k1 = 1u;
        const uint32_t k2 = k0 ^ k1 ^ 0x1BD11BDAu;
        uint32_t x0 = k0, x1 = (uint32_t)s + k1;
        tfr_p(x0,x1,13); tfr_p(x0,x1,15); tfr_p(x0,x1,26); tfr_p(x0,x1,6);
        x0 += k1; x1 += k2 + 1u;
        tfr_p(x0,x1,17); tfr_p(x0,x1,29); tfr_p(x0,x1,16); tfr_p(x0,x1,24);
        x0 += k2; x1 += k0 + 2u;
        tfr_p(x0,x1,13); tfr_p(x0,x1,15); tfr_p(x0,x1,26); tfr_p(x0,x1,6);
        x0 += k0; x1 += k1 + 3u;
        tfr_p(x0,x1,17); tfr_p(x0,x1,29); tfr_p(x0,x1,16); tfr_p(x0,x1,24);
        x0 += k1; x1 += k2 + 4u;
        tfr_p(x0,x1,13); tfr_p(x0,x1,15); tfr_p(x0,x1,26); tfr_p(x0,x1,6);
        uint32_t fk0 = x0 + k2;
        uint32_t fk1 = x1 + k0 + 5u;
        uint32_t fk2 = fk0 ^ fk1 ^ 0x1BD11BDAu;
        StepKey sk;
        sk.a = make_uint4(fk0, fk1, fk2, fk2 + 1u);
        sk.b = make_uint4(fk0 + 2u, fk1 + 3u, fk2 + 4u, fk0 + 5u);
        g_step_keys[s] = sk;
    }
}

// ---------------------------------------------------------------------------
// Main kernel: one thread per point, full trajectory in registers.
// Key for step s+1 is prefetched while step s computes.
// ---------------------------------------------------------------------------
__global__ void __launch_bounds__(256)
sbm_kernel(const float* __restrict__ xin,
           const int* __restrict__ t_ptr,
           const int* __restrict__ steps_ptr,
           float* __restrict__ out, int n) {
    int i = blockIdx.x * blockDim.x + threadIdx.x;
    if (i >= n) return;

    const int steps = *steps_ptr;
    const float dt = (float)(*t_ptr) / (float)steps;
    const float scale = 1.4142135381698608f * sqrtf(dt);   // sqrt2 * sqrt_dt
    const uint32_t one = umin((uint32_t)steps, 1u);        // opaque 1 for IMAD

    float x0 = xin[3 * i + 0];
    float x1 = xin[3 * i + 1];
    float x2 = xin[3 * i + 2];

    const uint32_t base = 3u * (uint32_t)i;

    StepKey k = g_step_keys[0];

    #pragma unroll 2
    for (int s = 0; s < steps; ++s) {
        const StepKey kn = g_step_keys[s + 1];   // prefetch next step's key

        // three fresh signed random words for this (point, step)
        const uint32_t c1k = base + k.a.y;   // counter + k1, shared init
        int32_t b0 = tf_sbits(k, c1k,      one);
        int32_t b1 = tf_sbits(k, c1k + 1u, one);
        int32_t b2 = tf_sbits(k, c1k + 2u, one);

        float v0 = normal_from_sbits(b0, scale);
        float v1 = normal_from_sbits(b1, scale);
        float v2 = normal_from_sbits(b2, scale);

        // Closed-form Heun step on the sphere (||x|| == 1):
        //   a = x.v, q' = v.v - a^2
        //   r1 = (a + q') / (1 + q')
        //   z  = alpha*x + beta*v,  beta = 1 - r1/2,
        //   alpha = beta - 0.5*a*(1 - r1)
        float a  = dot3(x0, x1, x2, v0, v1, v2);
        float q  = dot3(v0, v1, v2, v0, v1, v2);
        float qp = fmaf(-a, a, q);
        float r1 = (a + qp) * rcp_fast(1.0f + qp);
        float beta  = fmaf(-0.5f, r1, 1.0f);
        float t     = 1.0f - r1;
        float alpha = fmaf(-0.5f, a * t, beta);

        float z0 = fmaf(beta, v0, alpha * x0);
        float z1 = fmaf(beta, v1, alpha * x1);
        float z2 = fmaf(beta, v2, alpha * x2);

        float inv = rsqrt_fast(dot3(z0, z1, z2, z0, z1, z2));
        x0 = z0 * inv;
        x1 = z1 * inv;
        x2 = z2 * inv;

        k = kn;
    }

    out[3 * i + 0] = x0;
    out[3 * i + 1] = x1;
    out[3 * i + 2] = x2;
}

// ---------------------------------------------------------------------------
extern "C" void kernel_launch(void* const* d_in, const int* in_sizes, int n_in,
                              void* d_out, int out_size) {
    const float* x     = (const float*)d_in[0];
    const int*   t     = (const int*)d_in[1];
    const int*   steps = (const int*)d_in[2];
    const int n = in_sizes[0] / 3;

    keys_kernel<<<1, 256>>>(steps);

    const int threads = 256;
    const int blocks = (n + threads - 1) / threads;
    sbm_kernel<<<blocks, threads>>>(x, t, steps, (float*)d_out, n);
}

// round 15
// speedup vs baseline: 2.2226x; 1.0209x over previous
#include <cuda_runtime.h>
#include <cstdint>

// ============================================================================
// AmbientSphericalBrownianMotion — Stratonovich-Heun BM on S^2, N=4.2M pts,
// 100 steps. Bit-exact JAX threefry2x32 random bits (partitionable:
// bits0 ^ bits1). Issue-bound: threefry adds on IMAD (fma pipe) via opaque
// multiplier, SHF+LOP on alu pipe; projective Heun step (no rcp — scale
// factor absorbed by the final normalization); key prefetch + unroll-4.
// ============================================================================

#define MAX_STEPS 4096
struct __align__(16) StepKey {
    uint4 a;   // k0, k1, k2, k2+1
    uint4 b;   // k0+2, k1+3, k2+4, k0+5
};
__device__ StepKey g_step_keys[MAX_STEPS + 1];   // +1: unguarded s+1 prefetch

__device__ __forceinline__ uint32_t rotl32(uint32_t v, int r) {
    return __funnelshift_l(v, v, r);
}

// add via IMAD (fma pipe): d = a*one + c, with `one` runtime-opaque == 1.
__device__ __forceinline__ uint32_t imad1(uint32_t a, uint32_t one, uint32_t c) {
    uint32_t d;
    asm("mad.lo.u32 %0, %1, %2, %3;" : "=r"(d) : "r"(a), "r"(one), "r"(c));
    return d;
}

// threefry round: add on fma pipe (IMAD); rot+xor on alu pipe (SHF+LOP)
__device__ __forceinline__ void tfr(uint32_t& x0, uint32_t& x1, int r, uint32_t one) {
    x0 = imad1(x0, one, x1);
    x1 = rotl32(x1, r) ^ x0;
}

// JAX partitionable random_bits(32): bits0 ^ bits1, sign-flip folded into the
// final 3-input LOP3. All adds as IMAD: alu pipe sees 2 ops/round + 1 LOP3.
__device__ __forceinline__ int32_t tf_sbits(const StepKey& k, uint32_t x1init,
                                            uint32_t one) {
    uint32_t x0 = k.a.x;   // c0 = 0, so x0 = k0
    uint32_t x1 = x1init;  // c1 + k1, pre-added by caller
    tfr(x0, x1, 13, one); tfr(x0, x1, 15, one);
    tfr(x0, x1, 26, one); tfr(x0, x1, 6,  one);
    x0 = imad1(x0, one, k.a.y);  x1 = imad1(x1, one, k.a.w);  // +k1, +(k2+1)
    tfr(x0, x1, 17, one); tfr(x0, x1, 29, one);
    tfr(x0, x1, 16, one); tfr(x0, x1, 24, one);
    x0 = imad1(x0, one, k.a.z);  x1 = imad1(x1, one, k.b.x);  // +k2, +(k0+2)
    tfr(x0, x1, 13, one); tfr(x0, x1, 15, one);
    tfr(x0, x1, 26, one); tfr(x0, x1, 6,  one);
    x0 = imad1(x0, one, k.a.x);  x1 = imad1(x1, one, k.b.y);  // +k0, +(k1+3)
    tfr(x0, x1, 17, one); tfr(x0, x1, 29, one);
    tfr(x0, x1, 16, one); tfr(x0, x1, 24, one);
    x0 = imad1(x0, one, k.a.y);  x1 = imad1(x1, one, k.b.z);  // +k1, +(k2+4)
    tfr(x0, x1, 13, one); tfr(x0, x1, 15, one);
    tfr(x0, x1, 26, one); tfr(x0, x1, 6,  one);
    uint32_t o0 = imad1(x0, one, k.a.z);   // +k2
    uint32_t o1 = imad1(x1, one, k.b.w);   // +(k0+5)
    return (int32_t)(o0 ^ o1 ^ 0x80000000u);
}

// ---- fast-math primitives ----
__device__ __forceinline__ float lg2_fast(float x) {
    float r; asm("lg2.approx.f32 %0, %1;" : "=f"(r) : "f"(x)); return r;
}
__device__ __forceinline__ float rsqrt_fast(float x) {
    float r; asm("rsqrt.approx.f32 %0, %1;" : "=f"(r) : "f"(x)); return r;
}
__device__ __forceinline__ float sqrt_fast(float x) {
    float r; asm("sqrt.approx.f32 %0, %1;" : "=f"(r) : "f"(x)); return r;
}

// signed bits -> uniform(-1,1) -> sqrt2*erfinv(u)*sqrt_dt  (scale = sqrt2*sqrt_dt)
// Central branch always evaluated; rare tail handled warp-uniformly.
__device__ __forceinline__ float normal_from_sbits(int32_t sb, float scale) {
    float u  = __int2float_rn(sb) * 4.6566128730773926e-10f;   // 2^-31
    float us = u * scale;
    float L  = fmaxf(lg2_fast(fmaf(-u, u, 1.0f)), -23.0058f);  // log2(1-u^2)
    float m  = L * -0.69314718f;                               // w = -ln(1-u^2)
    float w  = m - 2.5f;
    float p;
    p =            2.81022636e-08f;
    p = fmaf(p, w, 3.43273939e-07f);
    p = fmaf(p, w, -3.5233877e-06f);
    p = fmaf(p, w, -4.39150654e-06f);
    p = fmaf(p, w, 0.00021858087f);
    p = fmaf(p, w, -0.00125372503f);
    p = fmaf(p, w, -0.00417768164f);
    p = fmaf(p, w, 0.246640727f);
    p = fmaf(p, w, 1.50140941f);
    bool tail = (m >= 5.0f);
    if (__any_sync(0xffffffffu, tail)) {
        float wt = sqrt_fast(m) - 3.0f;
        float pt;
        pt =             -0.000200214257f;
        pt = fmaf(pt, wt, 0.000100950558f);
        pt = fmaf(pt, wt, 0.00134934322f);
        pt = fmaf(pt, wt, -0.00367342844f);
        pt = fmaf(pt, wt, 0.00573950773f);
        pt = fmaf(pt, wt, -0.0076224613f);
        pt = fmaf(pt, wt, 0.00943887047f);
        pt = fmaf(pt, wt, 1.00167406f);
        pt = fmaf(pt, wt, 2.83297682f);
        p = tail ? pt : p;
    }
    return p * us;
}

__device__ __forceinline__ float dot3(float a0, float a1, float a2,
                                      float b0, float b1, float b2) {
    return fmaf(a2, b2, fmaf(a1, b1, a0 * b0));
}

// ---------------------------------------------------------------------------
// Pre-kernel: per-step folded keys + precomputed injection constants.
//   fold_in(key(1), s) = threefry((0,1),(0,s))
// ---------------------------------------------------------------------------
__device__ __forceinline__ void tfr_p(uint32_t& x0, uint32_t& x1, int r) {
    x0 += x1; x1 = rotl32(x1, r) ^ x0;
}
__global__ void keys_kernel(const int* __restrict__ steps_ptr) {
    int steps = *steps_ptr;
    if (steps > MAX_STEPS) steps = MAX_STEPS;
    // fill [0, steps] inclusive: entry [steps] is a valid dummy so the main
    // loop's s+1 prefetch never reads uninitialized/out-of-bounds memory
    for (int s = threadIdx.x; s <= steps; s += blockDim.x) {
        const uint32_t k0 = 0u, k1 = 1u;
        const uint32_t k2 = k0 ^ k1 ^ 0x1BD11BDAu;
        uint32_t x0 = k0, x1 = (uint32_t)s + k1;
        tfr_p(x0,x1,13); tfr_p(x0,x1,15); tfr_p(x0,x1,26); tfr_p(x0,x1,6);
        x0 += k1; x1 += k2 + 1u;
        tfr_p(x0,x1,17); tfr_p(x0,x1,29); tfr_p(x0,x1,16); tfr_p(x0,x1,24);
        x0 += k2; x1 += k0 + 2u;
        tfr_p(x0,x1,13); tfr_p(x0,x1,15); tfr_p(x0,x1,26); tfr_p(x0,x1,6);
        x0 += k0; x1 += k1 + 3u;
        tfr_p(x0,x1,17); tfr_p(x0,x1,29); tfr_p(x0,x1,16); tfr_p(x0,x1,24);
        x0 += k1; x1 += k2 + 4u;
        tfr_p(x0,x1,13); tfr_p(x0,x1,15); tfr_p(x0,x1,26); tfr_p(x0,x1,6);
        uint32_t fk0 = x0 + k2;
        uint32_t fk1 = x1 + k0 + 5u;
        uint32_t fk2 = fk0 ^ fk1 ^ 0x1BD11BDAu;
        StepKey sk;
        sk.a = make_uint4(fk0, fk1, fk2, fk2 + 1u);
        sk.b = make_uint4(fk0 + 2u, fk1 + 3u, fk2 + 4u, fk0 + 5u);
        g_step_keys[s] = sk;
    }
}

// ---------------------------------------------------------------------------
// Main kernel: one thread per point, full trajectory in registers.
// Projective Heun step: since x_new = z/||z||, z may be rescaled freely.
// Scaling by D = 1+q' removes the division entirely:
//   s  = 1 + q/2
//   a' = s - a                       (= D*alpha)
//   b' = s - a/2 - a^2/2             (= D*beta)
//   z  = a'*x + b'*v ;  x_new = z * rsqrt(z.z)
// ---------------------------------------------------------------------------
__global__ void __launch_bounds__(256)
sbm_kernel(const float* __restrict__ xin,
           const int* __restrict__ t_ptr,
           const int* __restrict__ steps_ptr,
           float* __restrict__ out, int n) {
    int i = blockIdx.x * blockDim.x + threadIdx.x;
    if (i >= n) return;

    const int steps = *steps_ptr;
    const float dt = (float)(*t_ptr) / (float)steps;
    const float scale = 1.4142135381698608f * sqrtf(dt);   // sqrt2 * sqrt_dt
    const uint32_t one = umin((uint32_t)steps, 1u);        // opaque 1 for IMAD

    float x0 = xin[3 * i + 0];
    float x1 = xin[3 * i + 1];
    float x2 = xin[3 * i + 2];

    const uint32_t base = 3u * (uint32_t)i;

    StepKey k = g_step_keys[0];

    #pragma unroll 4
    for (int s = 0; s < steps; ++s) {
        const StepKey kn = g_step_keys[s + 1];   // prefetch next step's key

        // three fresh signed random words for this (point, step)
        const uint32_t c1k = base + k.a.y;   // counter + k1, shared init
        int32_t b0 = tf_sbits(k, c1k,      one);
        int32_t b1 = tf_sbits(k, c1k + 1u, one);
        int32_t b2 = tf_sbits(k, c1k + 2u, one);

        float v0 = normal_from_sbits(b0, scale);
        float v1 = normal_from_sbits(b1, scale);
        float v2 = normal_from_sbits(b2, scale);

        // projective Heun step (no division)
        float a  = dot3(x0, x1, x2, v0, v1, v2);
        float q  = dot3(v0, v1, v2, v0, v1, v2);
        float sc = fmaf(0.5f, q, 1.0f);          // 1 + q/2
        float al = sc - a;                       // D*alpha
        float h  = 0.5f * a;
        float be = fmaf(-h, a, sc - h);          // D*beta

        float z0 = fmaf(be, v0, al * x0);
        float z1 = fmaf(be, v1, al * x1);
        float z2 = fmaf(be, v2, al * x2);

        float inv = rsqrt_fast(dot3(z0, z1, z2, z0, z1, z2));
        x0 = z0 * inv;
        x1 = z1 * inv;
        x2 = z2 * inv;

        k = kn;
    }

    out[3 * i + 0] = x0;
    out[3 * i + 1] = x1;
    out[3 * i + 2] = x2;
}

// ---------------------------------------------------------------------------
extern "C" void kernel_launch(void* const* d_in, const int* in_sizes, int n_in,
                              void* d_out, int out_size) {
    const float* x     = (const float*)d_in[0];
    const int*   t     = (const int*)d_in[1];
    const int*   steps = (const int*)d_in[2];
    const int n = in_sizes[0] / 3;

    keys_kernel<<<1, 256>>>(steps);

    const int threads = 256;
    const int blocks = (n + threads - 1) / threads;
    sbm_kernel<<<blocks, threads>>>(x, t, steps, (float*)d_out, n);
}

// round 16
// speedup vs baseline: 2.2355x; 1.0058x over previous
#include <cuda_runtime.h>
#include <cstdint>

// ============================================================================
// AmbientSphericalBrownianMotion — Stratonovich-Heun BM on S^2, N=4.2M pts,
// 100 steps. Bit-exact JAX threefry2x32 random bits (partitionable:
// bits0 ^ bits1). Issue-bound: threefry adds on IMAD (fma pipe) via opaque
// multiplier, SHF+LOP on alu pipe; projective Heun step (no rcp); fused
// lg2-domain erfinv (single FFMA from L to Horner w); key prefetch +
// unroll-2 (unroll-4 regressed issue efficiency in R15).
// ============================================================================

#define MAX_STEPS 4096
struct __align__(16) StepKey {
    uint4 a;   // k0, k1, k2, k2+1
    uint4 b;   // k0+2, k1+3, k2+4, k0+5
};
__device__ StepKey g_step_keys[MAX_STEPS + 1];   // +1: unguarded s+1 prefetch

__device__ __forceinline__ uint32_t rotl32(uint32_t v, int r) {
    return __funnelshift_l(v, v, r);
}

// add via IMAD (fma pipe): d = a*one + c, with `one` runtime-opaque == 1.
__device__ __forceinline__ uint32_t imad1(uint32_t a, uint32_t one, uint32_t c) {
    uint32_t d;
    asm("mad.lo.u32 %0, %1, %2, %3;" : "=r"(d) : "r"(a), "r"(one), "r"(c));
    return d;
}

// threefry round: add on fma pipe (IMAD); rot+xor on alu pipe (SHF+LOP)
__device__ __forceinline__ void tfr(uint32_t& x0, uint32_t& x1, int r, uint32_t one) {
    x0 = imad1(x0, one, x1);
    x1 = rotl32(x1, r) ^ x0;
}

// JAX partitionable random_bits(32): bits0 ^ bits1, sign-flip folded into the
// final 3-input LOP3. All adds as IMAD: alu pipe sees 2 ops/round + 1 LOP3.
__device__ __forceinline__ int32_t tf_sbits(const StepKey& k, uint32_t x1init,
                                            uint32_t one) {
    uint32_t x0 = k.a.x;   // c0 = 0, so x0 = k0
    uint32_t x1 = x1init;  // c1 + k1, pre-added by caller (IMAD)
    tfr(x0, x1, 13, one); tfr(x0, x1, 15, one);
    tfr(x0, x1, 26, one); tfr(x0, x1, 6,  one);
    x0 = imad1(x0, one, k.a.y);  x1 = imad1(x1, one, k.a.w);  // +k1, +(k2+1)
    tfr(x0, x1, 17, one); tfr(x0, x1, 29, one);
    tfr(x0, x1, 16, one); tfr(x0, x1, 24, one);
    x0 = imad1(x0, one, k.a.z);  x1 = imad1(x1, one, k.b.x);  // +k2, +(k0+2)
    tfr(x0, x1, 13, one); tfr(x0, x1, 15, one);
    tfr(x0, x1, 26, one); tfr(x0, x1, 6,  one);
    x0 = imad1(x0, one, k.a.x);  x1 = imad1(x1, one, k.b.y);  // +k0, +(k1+3)
    tfr(x0, x1, 17, one); tfr(x0, x1, 29, one);
    tfr(x0, x1, 16, one); tfr(x0, x1, 24, one);
    x0 = imad1(x0, one, k.a.y);  x1 = imad1(x1, one, k.b.z);  // +k1, +(k2+4)
    tfr(x0, x1, 13, one); tfr(x0, x1, 15, one);
    tfr(x0, x1, 26, one); tfr(x0, x1, 6,  one);
    uint32_t o0 = imad1(x0, one, k.a.z);   // +k2
    uint32_t o1 = imad1(x1, one, k.b.w);   // +(k0+5)
    return (int32_t)(o0 ^ o1 ^ 0x80000000u);
}

// ---- fast-math primitives ----
__device__ __forceinline__ float lg2_fast(float x) {
    float r; asm("lg2.approx.f32 %0, %1;" : "=f"(r) : "f"(x)); return r;
}
__device__ __forceinline__ float rsqrt_fast(float x) {
    float r; asm("rsqrt.approx.f32 %0, %1;" : "=f"(r) : "f"(x)); return r;
}
__device__ __forceinline__ float sqrt_fast(float x) {
    float r; asm("sqrt.approx.f32 %0, %1;" : "=f"(r) : "f"(x)); return r;
}

// signed bits -> uniform(-1,1) -> sqrt2*erfinv(u)*sqrt_dt  (scale = sqrt2*sqrt_dt)
// Entirely in lg2 domain: L = log2(1-u^2); central Horner w = L*(-ln2) - 2.5
// via one FFMA; tail test L <= -5/ln2; m = -ln(1-u^2) materialized only
// inside the (warp-uniform) tail block.
__device__ __forceinline__ float normal_from_sbits(int32_t sb, float scale) {
    float u  = __int2float_rn(sb) * 4.6566128730773926e-10f;   // 2^-31
    float us = u * scale;
    float L  = fmaxf(lg2_fast(fmaf(-u, u, 1.0f)), -23.0058f);  // log2(1-u^2)
    float w  = fmaf(L, -0.69314718f, -2.5f);                   // w_central
    float p;
    p =            2.81022636e-08f;
    p = fmaf(p, w, 3.43273939e-07f);
    p = fmaf(p, w, -3.5233877e-06f);
    p = fmaf(p, w, -4.39150654e-06f);
    p = fmaf(p, w, 0.00021858087f);
    p = fmaf(p, w, -0.00125372503f);
    p = fmaf(p, w, -0.00417768164f);
    p = fmaf(p, w, 0.246640727f);
    p = fmaf(p, w, 1.50140941f);
    bool tail = (L <= -7.2134752f);            // m >= 5
    if (__any_sync(0xffffffffu, tail)) {
        float m  = L * -0.69314718f;
        float wt = sqrt_fast(m) - 3.0f;
        float pt;
        pt =             -0.000200214257f;
        pt = fmaf(pt, wt, 0.000100950558f);
        pt = fmaf(pt, wt, 0.00134934322f);
        pt = fmaf(pt, wt, -0.00367342844f);
        pt = fmaf(pt, wt, 0.00573950773f);
        pt = fmaf(pt, wt, -0.0076224613f);
        pt = fmaf(pt, wt, 0.00943887047f);
        pt = fmaf(pt, wt, 1.00167406f);
        pt = fmaf(pt, wt, 2.83297682f);
        p = tail ? pt : p;
    }
    return p * us;
}

__device__ __forceinline__ float dot3(float a0, float a1, float a2,
                                      float b0, float b1, float b2) {
    return fmaf(a2, b2, fmaf(a1, b1, a0 * b0));
}

// ---------------------------------------------------------------------------
// Pre-kernel: per-step folded keys + precomputed injection constants.
//   fold_in(key(1), s) = threefry((0,1),(0,s))
// ---------------------------------------------------------------------------
__device__ __forceinline__ void tfr_p(uint32_t& x0, uint32_t& x1, int r) {
    x0 += x1; x1 = rotl32(x1, r) ^ x0;
}
__global__ void keys_kernel(const int* __restrict__ steps_ptr) {
    int steps = *steps_ptr;
    if (steps > MAX_STEPS) steps = MAX_STEPS;
    // fill [0, steps] inclusive: entry [steps] is a valid dummy so the main
    // loop's s+1 prefetch never reads uninitialized/out-of-bounds memory
    for (int s = threadIdx.x; s <= steps; s += blockDim.x) {
        const uint32_t k0 = 0u, k1 = 1u;
        const uint32_t k2 = k0 ^ k1 ^ 0x1BD11BDAu;
        uint32_t x0 = k0, x1 = (uint32_t)s + k1;
        tfr_p(x0,x1,13); tfr_p(x0,x1,15); tfr_p(x0,x1,26); tfr_p(x0,x1,6);
        x0 += k1; x1 += k2 + 1u;
        tfr_p(x0,x1,17); tfr_p(x0,x1,29); tfr_p(x0,x1,16); tfr_p(x0,x1,24);
        x0 += k2; x1 += k0 + 2u;
        tfr_p(x0,x1,13); tfr_p(x0,x1,15); tfr_p(x0,x1,26); tfr_p(x0,x1,6);
        x0 += k0; x1 += k1 + 3u;
        tfr_p(x0,x1,17); tfr_p(x0,x1,29); tfr_p(x0,x1,16); tfr_p(x0,x1,24);
        x0 += k1; x1 += k2 + 4u;
        tfr_p(x0,x1,13); tfr_p(x0,x1,15); tfr_p(x0,x1,26); tfr_p(x0,x1,6);
        uint32_t fk0 = x0 + k2;
        uint32_t fk1 = x1 + k0 + 5u;
        uint32_t fk2 = fk0 ^ fk1 ^ 0x1BD11BDAu;
        StepKey sk;
        sk.a = make_uint4(fk0, fk1, fk2, fk2 + 1u);
        sk.b = make_uint4(fk0 + 2u, fk1 + 3u, fk2 + 4u, fk0 + 5u);
        g_step_keys[s] = sk;
    }
}

// ---------------------------------------------------------------------------
// Main kernel: one thread per point, full trajectory in registers.
// Projective Heun step: z rescaled by D = 1+q' (absorbed by normalization):
//   s  = 1 + q/2 ;  a' = s - a ;  b' = s - a/2 - a^2/2
//   z  = a'*x + b'*v ;  x_new = z * rsqrt(z.z)
// ---------------------------------------------------------------------------
__global__ void __launch_bounds__(256)
sbm_kernel(const float* __restrict__ xin,
           const int* __restrict__ t_ptr,
           const int* __restrict__ steps_ptr,
           float* __restrict__ out, int n) {
    int i = blockIdx.x * blockDim.x + threadIdx.x;
    if (i >= n) return;

    const int steps = *steps_ptr;
    const float dt = (float)(*t_ptr) / (float)steps;
    const float scale = 1.4142135381698608f * sqrtf(dt);   // sqrt2 * sqrt_dt
    const uint32_t one = umin((uint32_t)steps, 1u);        // opaque 1 for IMAD

    float x0 = xin[3 * i + 0];
    float x1 = xin[3 * i + 1];
    float x2 = xin[3 * i + 2];

    const uint32_t base = 3u * (uint32_t)i;

    StepKey k = g_step_keys[0];

    #pragma unroll 2
    for (int s = 0; s < steps; ++s) {
        const StepKey kn = g_step_keys[s + 1];   // prefetch next step's key

        // three fresh signed random words for this (point, step);
        // counter+k1 inits forced onto IMAD to keep the alu pipe at its
        // SHF/LOP floor
        const uint32_t c1k = imad1(base, one, k.a.y);
        int32_t b0 = tf_sbits(k, c1k,                  one);
        int32_t b1 = tf_sbits(k, imad1(c1k, one, 1u),  one);
        int32_t b2 = tf_sbits(k, imad1(c1k, one, 2u),  one);

        float v0 = normal_from_sbits(b0, scale);
        float v1 = normal_from_sbits(b1, scale);
        float v2 = normal_from_sbits(b2, scale);

        // projective Heun step (no division)
        float a  = dot3(x0, x1, x2, v0, v1, v2);
        float q  = dot3(v0, v1, v2, v0, v1, v2);
        float sc = fmaf(0.5f, q, 1.0f);          // 1 + q/2
        float al = sc - a;                       // D*alpha
        float h  = 0.5f * a;
        float be = fmaf(-h, a, sc - h);          // D*beta

        float z0 = fmaf(be, v0, al * x0);
        float z1 = fmaf(be, v1, al * x1);
        float z2 = fmaf(be, v2, al * x2);

        float inv = rsqrt_fast(dot3(z0, z1, z2, z0, z1, z2));
        x0 = z0 * inv;
        x1 = z1 * inv;
        x2 = z2 * inv;

        k = kn;
    }

    out[3 * i + 0] = x0;
    out[3 * i + 1] = x1;
    out[3 * i + 2] = x2;
}

// ---------------------------------------------------------------------------
extern "C" void kernel_launch(void* const* d_in, const int* in_sizes, int n_in,
                              void* d_out, int out_size) {
    const float* x     = (const float*)d_in[0];
    const int*   t     = (const int*)d_in[1];
    const int*   steps = (const int*)d_in[2];
    const int n = in_sizes[0] / 3;

    keys_kernel<<<1, 256>>>(steps);

    const int threads = 256;
    const int blocks = (n + threads - 1) / threads;
    sbm_kernel<<<blocks, threads>>>(x, t, steps, (float*)d_out, n);
}